// round 1
// baseline (speedup 1.0000x reference)
#include <cuda_runtime.h>
#include <math.h>

#define BB 4
#define LL 1536
#define DD 768
#define HH 8
#define DQKc 64
#define DVc 96
#define NPOS 3071   // 2L-1

// ---------------- scratch (static device globals; no allocation) ----------------
__device__ float g_Q[(size_t)BB * LL * HH * DQKc];      // (B*L, 512)  Q (scaled)
__device__ float g_K[(size_t)BB * LL * HH * DQKc];      // (B*L, 512)
__device__ float g_V[(size_t)BB * LL * HH * DVc];       // (B*L, 768)
__device__ float g_pe[(size_t)NPOS * 96];               // (3071, 96)
__device__ float g_rK[(size_t)NPOS * HH * DQKc];        // (3071, 512)
__device__ float g_logits[(size_t)BB * HH * LL * LL];   // (32, 1536, 1536)
__device__ float g_attn[(size_t)BB * LL * HH * DVc];    // (B*L, 768)

// ---------------- positional features ----------------
__device__ __forceinline__ float gamma_pdf(float x, float cm1, float rate, float lognorm) {
    if (x <= 0.0f) return 0.0f;
    return expf(cm1 * logf(x) - rate * x - lognorm);
}

__global__ void pe_kernel(float* __restrict__ pe) {
    int idx = blockIdx.x * blockDim.x + threadIdx.x;
    if (idx >= NPOS) return;
    float p = (float)(idx - (LL - 1));
    float ap = fabsf(p);
    float sg = (p > 0.f) ? 1.f : ((p < 0.f) ? -1.f : 0.f);
    float max_range = log2f((float)LL);
    float* row = pe + (size_t)idx * 96;
    #pragma unroll 1
    for (int i = 0; i < 16; i++) {
        // exponential
        float hl = exp2f(3.0f + (max_range - 3.0f) * (float)i * (1.0f / 15.0f));
        float fe = exp2f(-ap / hl);
        // central mask
        float cw = exp2f((float)(i + 1)) - 1.0f;
        float fc = (cw > ap) ? 1.0f : 0.0f;
        // gamma: mean = 96*(i+1), stddev = 48
        float k1 = (float)(i + 1);
        float conc = 4.0f * k1 * k1;
        float rate = k1 * (1.0f / 24.0f);
        float lognorm = lgammaf(conc) - conc * logf(rate);
        float cm1 = conc - 1.0f;
        // integer argmax of log-concave pdf = floor/ceil of continuous mode
        float mode = cm1 / rate;
        float t0 = fminf(fmaxf(floorf(mode), 0.0f), (float)(LL - 1));
        float t1 = fminf(t0 + 1.0f, (float)(LL - 1));
        float mx = fmaxf(gamma_pdf(t0, cm1, rate, lognorm),
                         gamma_pdf(t1, cm1, rate, lognorm)) + 1e-8f;
        float fg = (gamma_pdf(ap, cm1, rate, lognorm) + 1e-8f) / mx;
        row[i]      = fe;      row[16 + i] = fc;      row[32 + i] = fg;
        row[48 + i] = sg * fe; row[64 + i] = sg * fc; row[80 + i] = sg * fg;
    }
}

// ---------------- generic tiled SGEMM (NN), optional batch over (b,h) ----------------
// C[i,j] = alpha * sum_k A[i,k] * B[k,j]  (+ bias[j])
__global__ __launch_bounds__(256) void sgemm_kernel(
    const float* __restrict__ A, int lda, long long sA,
    const float* __restrict__ B, int ldb, long long sB1, long long sB2,
    float* __restrict__ C, int ldc, long long sC1, long long sC2,
    int M, int N, int K, float alpha, const float* __restrict__ bias)
{
    __shared__ float As[16][64];   // As[k][i]
    __shared__ float Bs[16][64];   // Bs[k][j]

    int z = blockIdx.z;
    int zb = z >> 3, zh = z & 7;
    A += (size_t)z * sA;
    B += (size_t)zb * sB1 + (size_t)zh * sB2;
    C += (size_t)zb * sC1 + (size_t)zh * sC2;

    int i0 = blockIdx.y * 64, j0 = blockIdx.x * 64;
    int tid = threadIdx.x;
    int tx = tid & 15, ty = tid >> 4;

    int ar = tid >> 2, ac = (tid & 3) * 4;   // A loader
    int br = tid >> 4, bc = (tid & 15) * 4;  // B loader

    float acc[4][4] = {};

    for (int kk = 0; kk < K; kk += 16) {
        #pragma unroll
        for (int t = 0; t < 4; t++) {
            int kpos = kk + ac + t;
            float v = 0.0f;
            if (i0 + ar < M && kpos < K) v = A[(size_t)(i0 + ar) * lda + kpos];
            As[ac + t][ar] = v;
        }
        #pragma unroll
        for (int t = 0; t < 4; t++) {
            int kpos = kk + br;
            int j = j0 + bc + t;
            float v = 0.0f;
            if (kpos < K && j < N) v = B[(size_t)kpos * ldb + j];
            Bs[br][bc + t] = v;
        }
        __syncthreads();
        #pragma unroll
        for (int k = 0; k < 16; k++) {
            float4 a4 = *(const float4*)&As[k][ty * 4];
            float4 b4 = *(const float4*)&Bs[k][tx * 4];
            float av[4] = {a4.x, a4.y, a4.z, a4.w};
            float bv[4] = {b4.x, b4.y, b4.z, b4.w};
            #pragma unroll
            for (int a = 0; a < 4; a++)
                #pragma unroll
                for (int b = 0; b < 4; b++)
                    acc[a][b] += av[a] * bv[b];
        }
        __syncthreads();
    }

    #pragma unroll
    for (int a = 0; a < 4; a++) {
        int i = i0 + ty * 4 + a;
        if (i >= M) continue;
        #pragma unroll
        for (int b = 0; b < 4; b++) {
            int j = j0 + tx * 4 + b;
            if (j >= N) continue;
            float v = alpha * acc[a][b];
            if (bias) v += bias[j];
            C[(size_t)i * ldc + j] = v;
        }
    }
}

// ---------------- fused score kernel: content + shifted-rel band ----------------
// logits[z,i,j] = (Q+rwb)_i . K_j  +  (Q+rrb)_i . rK_{j-i+L-1}
// Implemented as (Q+rwb).K + (Q+rwb).band + delta.band, delta = rrb - rwb
__global__ __launch_bounds__(256) void score_kernel(
    const float* __restrict__ Q, const float* __restrict__ K,
    const float* __restrict__ rK, const float* __restrict__ rwb,
    const float* __restrict__ rrb, float* __restrict__ logits)
{
    __shared__ float sQ[32 * 64];    // sQ[d][ii]  (Q + rwb)
    __shared__ float sK[32 * 64];    // sK[d][jj]
    __shared__ float sB[32 * 128];   // sB[d][r], band rows r=0..126
    __shared__ float sBD[128];       // delta . band_r
    __shared__ float sDelta[64];

    int z = blockIdx.z;
    int b = z >> 3, h = z & 7;
    int i0 = blockIdx.y * 64, j0 = blockIdx.x * 64;
    int tid = threadIdx.x;
    int tx = tid & 15, ty = tid >> 4;

    const float* Qb = Q + ((size_t)b * LL) * (HH * DQKc) + h * DQKc;
    const float* Kb = K + ((size_t)b * LL) * (HH * DQKc) + h * DQKc;
    int k0 = (LL - 1) + j0 - i0 - 63;   // band row r -> rK row k0+r (always in [0, 2L-2])

    if (tid < 64)  sDelta[tid] = rrb[h * 64 + tid] - rwb[h * 64 + tid];
    if (tid < 128) sBD[tid] = 0.0f;
    __syncthreads();

    float acc[4][4] = {};
    float accR[4][4] = {};
    int rb = 4 * (tx - ty) + 60;   // band index base for this thread (+o, o=0..6)

    for (int dc = 0; dc < 2; dc++) {
        int d0 = dc * 32;
        // load Q (+rwb) and K tiles, transposed to [d][row]
        {
            int ii = tid >> 2;
            int dl = (tid & 3) * 8;
            const float* qs = Qb + (size_t)(i0 + ii) * (HH * DQKc) + d0 + dl;
            const float* ks = Kb + (size_t)(j0 + ii) * (HH * DQKc) + d0 + dl;
            const float* wb = rwb + h * 64 + d0 + dl;
            #pragma unroll
            for (int v = 0; v < 2; v++) {
                float4 q4 = *(const float4*)(qs + v * 4);
                float4 w4 = *(const float4*)(wb + v * 4);
                sQ[(dl + v * 4 + 0) * 64 + ii] = q4.x + w4.x;
                sQ[(dl + v * 4 + 1) * 64 + ii] = q4.y + w4.y;
                sQ[(dl + v * 4 + 2) * 64 + ii] = q4.z + w4.z;
                sQ[(dl + v * 4 + 3) * 64 + ii] = q4.w + w4.w;
                float4 k4 = *(const float4*)(ks + v * 4);
                sK[(dl + v * 4 + 0) * 64 + ii] = k4.x;
                sK[(dl + v * 4 + 1) * 64 + ii] = k4.y;
                sK[(dl + v * 4 + 2) * 64 + ii] = k4.z;
                sK[(dl + v * 4 + 3) * 64 + ii] = k4.w;
            }
        }
        // load band (127 rows x 32 d), transposed
        {
            int r = tid >> 1;
            int dh = (tid & 1) * 16;
            if (r < 127) {
                const float* bs = rK + (size_t)(k0 + r) * (HH * DQKc) + h * DQKc + d0 + dh;
                #pragma unroll
                for (int v = 0; v < 4; v++) {
                    float4 x4 = *(const float4*)(bs + v * 4);
                    sB[(dh + v * 4 + 0) * 128 + r] = x4.x;
                    sB[(dh + v * 4 + 1) * 128 + r] = x4.y;
                    sB[(dh + v * 4 + 2) * 128 + r] = x4.z;
                    sB[(dh + v * 4 + 3) * 128 + r] = x4.w;
                }
            }
        }
        __syncthreads();

        // delta . band_r (partial over this d-chunk)
        if (tid < 127) {
            float s = 0.0f;
            #pragma unroll
            for (int d = 0; d < 32; d++) s += sDelta[d0 + d] * sB[d * 128 + tid];
            sBD[tid] += s;
        }

        // main MAC loop
        #pragma unroll 4
        for (int d = 0; d < 32; d++) {
            float4 a4 = *(const float4*)&sQ[d * 64 + ty * 4];
            float4 k4 = *(const float4*)&sK[d * 64 + tx * 4];
            float av[4] = {a4.x, a4.y, a4.z, a4.w};
            float kv[4] = {k4.x, k4.y, k4.z, k4.w};
            float bv[7];
            #pragma unroll
            for (int o = 0; o < 7; o++) bv[o] = sB[d * 128 + rb + o];
            #pragma unroll
            for (int a = 0; a < 4; a++)
                #pragma unroll
                for (int c = 0; c < 4; c++) {
                    acc[a][c]  += av[a] * kv[c];
                    accR[a][c] += av[a] * bv[c - a + 3];
                }
        }
        __syncthreads();
    }

    float* out = logits + (size_t)z * LL * LL;
    #pragma unroll
    for (int a = 0; a < 4; a++) {
        int i = i0 + ty * 4 + a;
        #pragma unroll
        for (int c = 0; c < 4; c++) {
            int j = j0 + tx * 4 + c;
            out[(size_t)i * LL + j] = acc[a][c] + accR[a][c] + sBD[rb + 3 + c - a];
        }
    }
}

// ---------------- row softmax (in place), one block per row of 1536 ----------------
__global__ __launch_bounds__(256) void softmax_kernel(float* __restrict__ logits) {
    __shared__ float red[256];
    size_t row = blockIdx.x;
    float* p = logits + row * LL;
    int tid = threadIdx.x;
    float v[6];
    float mx = -1e30f;
    #pragma unroll
    for (int t = 0; t < 6; t++) { v[t] = p[tid + t * 256]; mx = fmaxf(mx, v[t]); }
    red[tid] = mx; __syncthreads();
    for (int s = 128; s > 0; s >>= 1) {
        if (tid < s) red[tid] = fmaxf(red[tid], red[tid + s]);
        __syncthreads();
    }
    mx = red[0]; __syncthreads();
    float sum = 0.0f;
    #pragma unroll
    for (int t = 0; t < 6; t++) { v[t] = expf(v[t] - mx); sum += v[t]; }
    red[tid] = sum; __syncthreads();
    for (int s = 128; s > 0; s >>= 1) {
        if (tid < s) red[tid] += red[tid + s];
        __syncthreads();
    }
    float inv = 1.0f / red[0];
    #pragma unroll
    for (int t = 0; t < 6; t++) p[tid + t * 256] = v[t] * inv;
}

// ---------------- launch ----------------
extern "C" void kernel_launch(void* const* d_in, const int* in_sizes, int n_in,
                              void* d_out, int out_size) {
    (void)in_sizes; (void)n_in; (void)out_size;
    const float* x     = (const float*)d_in[0];
    const float* Qw    = (const float*)d_in[1];
    const float* Kw    = (const float*)d_in[2];
    const float* Vw    = (const float*)d_in[3];
    const float* outw  = (const float*)d_in[4];
    const float* outb  = (const float*)d_in[5];
    const float* relKw = (const float*)d_in[6];
    const float* rwb   = (const float*)d_in[7];
    const float* rrb   = (const float*)d_in[8];

    float *pQ, *pK, *pV, *ppe, *prK, *plog, *pattn;
    cudaGetSymbolAddress((void**)&pQ,    g_Q);
    cudaGetSymbolAddress((void**)&pK,    g_K);
    cudaGetSymbolAddress((void**)&pV,    g_V);
    cudaGetSymbolAddress((void**)&ppe,   g_pe);
    cudaGetSymbolAddress((void**)&prK,   g_rK);
    cudaGetSymbolAddress((void**)&plog,  g_logits);
    cudaGetSymbolAddress((void**)&pattn, g_attn);

    // 1. positional features (3071 x 96)
    pe_kernel<<<(NPOS + 127) / 128, 128>>>(ppe);

    // 2. r_K = pe @ rel_K_w : (3071 x 512), K=96
    sgemm_kernel<<<dim3(8, 48, 1), 256>>>(ppe, 96, 0, relKw, 512, 0, 0,
                                          prK, 512, 0, 0, NPOS, 512, 96, 1.0f, nullptr);

    // 3. projections: Q (scaled by dqk^-0.5 = 0.125), K, V
    sgemm_kernel<<<dim3(8, 96, 1), 256>>>(x, DD, 0, Qw, HH * DQKc, 0, 0,
                                          pQ, HH * DQKc, 0, 0, BB * LL, HH * DQKc, DD, 0.125f, nullptr);
    sgemm_kernel<<<dim3(8, 96, 1), 256>>>(x, DD, 0, Kw, HH * DQKc, 0, 0,
                                          pK, HH * DQKc, 0, 0, BB * LL, HH * DQKc, DD, 1.0f, nullptr);
    sgemm_kernel<<<dim3(12, 96, 1), 256>>>(x, DD, 0, Vw, HH * DVc, 0, 0,
                                           pV, HH * DVc, 0, 0, BB * LL, HH * DVc, DD, 1.0f, nullptr);

    // 4. fused content + shifted-rel scores -> logits
    score_kernel<<<dim3(24, 24, 32), 256>>>(pQ, pK, prK, rwb, rrb, plog);

    // 5. softmax over j
    softmax_kernel<<<BB * HH * LL, 256>>>(plog);

    // 6. attn = P @ V, batched over (b,h)
    sgemm_kernel<<<dim3(2, 24, 32), 256>>>(plog, LL, (long long)LL * LL,
                                           pV, HH * DVc, (long long)LL * HH * DVc, DVc,
                                           pattn, HH * DVc, (long long)LL * HH * DVc, DVc,
                                           LL, DVc, LL, 1.0f, nullptr);

    // 7. out = attn @ out_w + out_b  -> d_out
    sgemm_kernel<<<dim3(12, 96, 1), 256>>>(pattn, DD, 0, outw, DD, 0, 0,
                                           (float*)d_out, DD, 0, 0, BB * LL, DD, DD, 1.0f, outb);
}

// round 2
// speedup vs baseline: 1.4479x; 1.4479x over previous
#include <cuda_runtime.h>
#include <math.h>

#define BB 4
#define LL 1536
#define DD 768
#define HH 8
#define DQKc 64
#define DVc 96
#define NPOS 3071   // 2L-1

// ---------------- scratch (static device globals; no allocation) ----------------
__device__ float g_Q[(size_t)BB * LL * HH * DQKc];      // (B*L, 512)  Q (scaled)
__device__ float g_K[(size_t)BB * LL * HH * DQKc];      // (B*L, 512)
__device__ float g_V[(size_t)BB * LL * HH * DVc];       // (B*L, 768)
__device__ float g_pe[(size_t)NPOS * 96];               // (3071, 96)
__device__ float g_rK[(size_t)NPOS * HH * DQKc];        // (3071, 512)
__device__ float g_logits[(size_t)BB * HH * LL * LL];   // (32, 1536, 1536)
__device__ float g_attn[(size_t)BB * LL * HH * DVc];    // (B*L, 768)

// ---------------- positional features ----------------
__device__ __forceinline__ float gamma_pdf(float x, float cm1, float rate, float lognorm) {
    if (x <= 0.0f) return 0.0f;
    return expf(cm1 * logf(x) - rate * x - lognorm);
}

__global__ void pe_kernel(float* __restrict__ pe) {
    int idx = blockIdx.x * blockDim.x + threadIdx.x;
    if (idx >= NPOS) return;
    float p = (float)(idx - (LL - 1));
    float ap = fabsf(p);
    float sg = (p > 0.f) ? 1.f : ((p < 0.f) ? -1.f : 0.f);
    float max_range = log2f((float)LL);
    float* row = pe + (size_t)idx * 96;
    #pragma unroll 1
    for (int i = 0; i < 16; i++) {
        float hl = exp2f(3.0f + (max_range - 3.0f) * (float)i * (1.0f / 15.0f));
        float fe = exp2f(-ap / hl);
        float cw = exp2f((float)(i + 1)) - 1.0f;
        float fc = (cw > ap) ? 1.0f : 0.0f;
        float k1 = (float)(i + 1);
        float conc = 4.0f * k1 * k1;
        float rate = k1 * (1.0f / 24.0f);
        float lognorm = lgammaf(conc) - conc * logf(rate);
        float cm1 = conc - 1.0f;
        float mode = cm1 / rate;
        float t0 = fminf(fmaxf(floorf(mode), 0.0f), (float)(LL - 1));
        float t1 = fminf(t0 + 1.0f, (float)(LL - 1));
        float mx = fmaxf(gamma_pdf(t0, cm1, rate, lognorm),
                         gamma_pdf(t1, cm1, rate, lognorm)) + 1e-8f;
        float fg = (gamma_pdf(ap, cm1, rate, lognorm) + 1e-8f) / mx;
        row[i]      = fe;      row[16 + i] = fc;      row[32 + i] = fg;
        row[48 + i] = sg * fe; row[64 + i] = sg * fc; row[80 + i] = sg * fg;
    }
}

// ---------------- high-throughput SGEMM: 128 x BN tile, 8 x TN per thread ----------------
// C[i,j] = alpha * sum_k A[i,k] * B[k,j] (+ bias[j]); batched over blockIdx.z like before.
// Requires: K % 8 == 0, N covered exactly by grid*BN, lda/ldb give 16B-aligned float4 rows
// (all call sites satisfy this). Only M may be ragged (rK with M=3071).
template<int BN, int TN>
__global__ __launch_bounds__(256) void sgemm128(
    const float* __restrict__ A, int lda, long long sA,
    const float* __restrict__ B, int ldb, long long sB1, long long sB2,
    float* __restrict__ C, int ldc, long long sC1, long long sC2,
    int M, int N, int K, float alpha, const float* __restrict__ bias)
{
    constexpr int BK = 8;
    __shared__ float As[BK][128];
    __shared__ float Bs[BK][BN];

    int z = blockIdx.z;
    int zb = z >> 3, zh = z & 7;
    A += (size_t)z * sA;
    B += (size_t)zb * sB1 + (size_t)zh * sB2;
    C += (size_t)zb * sC1 + (size_t)zh * sC2;

    int i0 = blockIdx.y * 128, j0 = blockIdx.x * BN;
    int tid = threadIdx.x;
    int tx = tid & 15, ty = tid >> 4;

    // A loader: each of 256 threads loads one float4: row ar, k-offset ak
    int ar = tid >> 1, ak = (tid & 1) * 4;
    bool aIn = (i0 + ar < M);

    // B loader
    int bk, bc; bool bAct;
    if (BN == 128) { bk = tid >> 5; bc = (tid & 31) * 4; bAct = true; }
    else           { bk = tid / 24; bc = (tid % 24) * 4; bAct = (tid < 192); }  // BN==96

    float4 aR = make_float4(0, 0, 0, 0), bR = make_float4(0, 0, 0, 0);
    if (aIn)  aR = *(const float4*)&A[(size_t)(i0 + ar) * lda + ak];
    if (bAct) bR = *(const float4*)&B[(size_t)bk * ldb + j0 + bc];

    float acc[8][TN];
    #pragma unroll
    for (int a = 0; a < 8; a++)
        #pragma unroll
        for (int b = 0; b < TN; b++) acc[a][b] = 0.0f;

    for (int kk = 0; kk < K; kk += BK) {
        // stage regs -> smem
        As[ak + 0][ar] = aR.x; As[ak + 1][ar] = aR.y;
        As[ak + 2][ar] = aR.z; As[ak + 3][ar] = aR.w;
        if (bAct) {
            Bs[bk][bc + 0] = bR.x; Bs[bk][bc + 1] = bR.y;
            Bs[bk][bc + 2] = bR.z; Bs[bk][bc + 3] = bR.w;
        }
        __syncthreads();
        // prefetch next tile into regs (latency hidden by compute below)
        if (kk + BK < K) {
            if (aIn)  aR = *(const float4*)&A[(size_t)(i0 + ar) * lda + kk + BK + ak];
            if (bAct) bR = *(const float4*)&B[(size_t)(kk + BK + bk) * ldb + j0 + bc];
        }
        #pragma unroll
        for (int k = 0; k < BK; k++) {
            float a[8];
            float4 a0 = *(const float4*)&As[k][ty * 8];
            float4 a1 = *(const float4*)&As[k][ty * 8 + 4];
            a[0] = a0.x; a[1] = a0.y; a[2] = a0.z; a[3] = a0.w;
            a[4] = a1.x; a[5] = a1.y; a[6] = a1.z; a[7] = a1.w;
            float b[TN];
            if (BN == 128) {
                float4 b0 = *(const float4*)&Bs[k][tx * 8];
                float4 b1 = *(const float4*)&Bs[k][tx * 8 + 4];
                b[0] = b0.x; b[1] = b0.y; b[2] = b0.z; b[3] = b0.w;
                b[4] = b1.x; b[5] = b1.y; b[6] = b1.z; b[7 < TN ? 7 : 0] = b1.w;
            } else {
                float2 p0 = *(const float2*)&Bs[k][tx * 6];
                float2 p1 = *(const float2*)&Bs[k][tx * 6 + 2];
                float2 p2 = *(const float2*)&Bs[k][tx * 6 + 4];
                b[0] = p0.x; b[1] = p0.y; b[2] = p1.x;
                b[3] = p1.y; b[4] = p2.x; b[5 < TN ? 5 : 0] = p2.y;
            }
            #pragma unroll
            for (int ai = 0; ai < 8; ai++)
                #pragma unroll
                for (int bi = 0; bi < TN; bi++)
                    acc[ai][bi] += a[ai] * b[bi];
        }
        __syncthreads();
    }

    #pragma unroll
    for (int a = 0; a < 8; a++) {
        int i = i0 + ty * 8 + a;
        if (i >= M) continue;
        #pragma unroll
        for (int b = 0; b < TN; b++) {
            int j = j0 + tx * TN + b;
            float v = alpha * acc[a][b];
            if (bias) v += bias[j];
            C[(size_t)i * ldc + j] = v;
        }
    }
}

// ---------------- fused score kernel: content + shifted-rel band ----------------
// logits[z,i,j] = (Q+rwb)_i . K_j  +  (Q+rrb)_i . rK_{j-i+L-1}
// Implemented as (Q+rwb).K + (Q+rwb).band + delta.band, delta = rrb - rwb
__global__ __launch_bounds__(256) void score_kernel(
    const float* __restrict__ Q, const float* __restrict__ K,
    const float* __restrict__ rK, const float* __restrict__ rwb,
    const float* __restrict__ rrb, float* __restrict__ logits)
{
    __shared__ float sQ[32 * 64];    // sQ[d][ii]  (Q + rwb)
    __shared__ float sK[32 * 64];    // sK[d][jj]
    __shared__ float sB[32 * 128];   // sB[d][r], band rows r=0..126
    __shared__ float sBD[128];       // delta . band_r
    __shared__ float sDelta[64];

    int z = blockIdx.z;
    int b = z >> 3, h = z & 7;
    int i0 = blockIdx.y * 64, j0 = blockIdx.x * 64;
    int tid = threadIdx.x;
    int tx = tid & 15, ty = tid >> 4;

    const float* Qb = Q + ((size_t)b * LL) * (HH * DQKc) + h * DQKc;
    const float* Kb = K + ((size_t)b * LL) * (HH * DQKc) + h * DQKc;
    int k0 = (LL - 1) + j0 - i0 - 63;

    if (tid < 64)  sDelta[tid] = rrb[h * 64 + tid] - rwb[h * 64 + tid];
    if (tid < 128) sBD[tid] = 0.0f;
    __syncthreads();

    float acc[4][4] = {};
    float accR[4][4] = {};
    int rb = 4 * (tx - ty) + 60;   // 4-aligned, in [0, 120]

    for (int dc = 0; dc < 2; dc++) {
        int d0 = dc * 32;
        {
            int ii = tid >> 2;
            int dl = (tid & 3) * 8;
            const float* qs = Qb + (size_t)(i0 + ii) * (HH * DQKc) + d0 + dl;
            const float* ks = Kb + (size_t)(j0 + ii) * (HH * DQKc) + d0 + dl;
            const float* wb = rwb + h * 64 + d0 + dl;
            #pragma unroll
            for (int v = 0; v < 2; v++) {
                float4 q4 = *(const float4*)(qs + v * 4);
                float4 w4 = *(const float4*)(wb + v * 4);
                sQ[(dl + v * 4 + 0) * 64 + ii] = q4.x + w4.x;
                sQ[(dl + v * 4 + 1) * 64 + ii] = q4.y + w4.y;
                sQ[(dl + v * 4 + 2) * 64 + ii] = q4.z + w4.z;
                sQ[(dl + v * 4 + 3) * 64 + ii] = q4.w + w4.w;
                float4 k4 = *(const float4*)(ks + v * 4);
                sK[(dl + v * 4 + 0) * 64 + ii] = k4.x;
                sK[(dl + v * 4 + 1) * 64 + ii] = k4.y;
                sK[(dl + v * 4 + 2) * 64 + ii] = k4.z;
                sK[(dl + v * 4 + 3) * 64 + ii] = k4.w;
            }
        }
        {
            int r = tid >> 1;
            int dh = (tid & 1) * 16;
            if (r < 127) {
                const float* bs = rK + (size_t)(k0 + r) * (HH * DQKc) + h * DQKc + d0 + dh;
                #pragma unroll
                for (int v = 0; v < 4; v++) {
                    float4 x4 = *(const float4*)(bs + v * 4);
                    sB[(dh + v * 4 + 0) * 128 + r] = x4.x;
                    sB[(dh + v * 4 + 1) * 128 + r] = x4.y;
                    sB[(dh + v * 4 + 2) * 128 + r] = x4.z;
                    sB[(dh + v * 4 + 3) * 128 + r] = x4.w;
                }
            }
        }
        __syncthreads();

        if (tid < 127) {
            float s = 0.0f;
            #pragma unroll
            for (int d = 0; d < 32; d++) s += sDelta[d0 + d] * sB[d * 128 + tid];
            sBD[tid] += s;
        }

        #pragma unroll 4
        for (int d = 0; d < 32; d++) {
            float4 a4 = *(const float4*)&sQ[d * 64 + ty * 4];
            float4 k4 = *(const float4*)&sK[d * 64 + tx * 4];
            float av[4] = {a4.x, a4.y, a4.z, a4.w};
            float kv[4] = {k4.x, k4.y, k4.z, k4.w};
            // band values rb..rb+6 via two vector loads (rb is 4-aligned)
            float4 f0 = *(const float4*)&sB[d * 128 + rb];
            float4 f1 = *(const float4*)&sB[d * 128 + rb + 4];
            float bv[8] = {f0.x, f0.y, f0.z, f0.w, f1.x, f1.y, f1.z, f1.w};
            #pragma unroll
            for (int a = 0; a < 4; a++)
                #pragma unroll
                for (int c = 0; c < 4; c++) {
                    acc[a][c]  += av[a] * kv[c];
                    accR[a][c] += av[a] * bv[c - a + 3];
                }
        }
        __syncthreads();
    }

    float* out = logits + (size_t)z * LL * LL;
    #pragma unroll
    for (int a = 0; a < 4; a++) {
        int i = i0 + ty * 4 + a;
        #pragma unroll
        for (int c = 0; c < 4; c++) {
            int j = j0 + tx * 4 + c;
            out[(size_t)i * LL + j] = acc[a][c] + accR[a][c] + sBD[rb + 3 + c - a];
        }
    }
}

// ---------------- row softmax (in place), one block per row of 1536 ----------------
__global__ __launch_bounds__(256) void softmax_kernel(float* __restrict__ logits) {
    __shared__ float red[256];
    size_t row = blockIdx.x;
    float* p = logits + row * LL;
    int tid = threadIdx.x;
    float v[6];
    float mx = -1e30f;
    #pragma unroll
    for (int t = 0; t < 6; t++) { v[t] = p[tid + t * 256]; mx = fmaxf(mx, v[t]); }
    red[tid] = mx; __syncthreads();
    for (int s = 128; s > 0; s >>= 1) {
        if (tid < s) red[tid] = fmaxf(red[tid], red[tid + s]);
        __syncthreads();
    }
    mx = red[0]; __syncthreads();
    float sum = 0.0f;
    #pragma unroll
    for (int t = 0; t < 6; t++) { v[t] = expf(v[t] - mx); sum += v[t]; }
    red[tid] = sum; __syncthreads();
    for (int s = 128; s > 0; s >>= 1) {
        if (tid < s) red[tid] += red[tid + s];
        __syncthreads();
    }
    float inv = 1.0f / red[0];
    #pragma unroll
    for (int t = 0; t < 6; t++) p[tid + t * 256] = v[t] * inv;
}

// ---------------- launch ----------------
extern "C" void kernel_launch(void* const* d_in, const int* in_sizes, int n_in,
                              void* d_out, int out_size) {
    (void)in_sizes; (void)n_in; (void)out_size;
    const float* x     = (const float*)d_in[0];
    const float* Qw    = (const float*)d_in[1];
    const float* Kw    = (const float*)d_in[2];
    const float* Vw    = (const float*)d_in[3];
    const float* outw  = (const float*)d_in[4];
    const float* outb  = (const float*)d_in[5];
    const float* relKw = (const float*)d_in[6];
    const float* rwb   = (const float*)d_in[7];
    const float* rrb   = (const float*)d_in[8];

    float *pQ, *pK, *pV, *ppe, *prK, *plog, *pattn;
    cudaGetSymbolAddress((void**)&pQ,    g_Q);
    cudaGetSymbolAddress((void**)&pK,    g_K);
    cudaGetSymbolAddress((void**)&pV,    g_V);
    cudaGetSymbolAddress((void**)&ppe,   g_pe);
    cudaGetSymbolAddress((void**)&prK,   g_rK);
    cudaGetSymbolAddress((void**)&plog,  g_logits);
    cudaGetSymbolAddress((void**)&pattn, g_attn);

    // 1. positional features (3071 x 96)
    pe_kernel<<<(NPOS + 127) / 128, 128>>>(ppe);

    // 2. r_K = pe @ rel_K_w : (3071 x 512), K=96
    sgemm128<128, 8><<<dim3(4, 24, 1), 256>>>(ppe, 96, 0, relKw, 512, 0, 0,
                                              prK, 512, 0, 0, NPOS, 512, 96, 1.0f, nullptr);

    // 3. projections: Q (scaled by dqk^-0.5 = 0.125), K, V
    sgemm128<128, 8><<<dim3(4, 48, 1), 256>>>(x, DD, 0, Qw, HH * DQKc, 0, 0,
                                              pQ, HH * DQKc, 0, 0, BB * LL, HH * DQKc, DD, 0.125f, nullptr);
    sgemm128<128, 8><<<dim3(4, 48, 1), 256>>>(x, DD, 0, Kw, HH * DQKc, 0, 0,
                                              pK, HH * DQKc, 0, 0, BB * LL, HH * DQKc, DD, 1.0f, nullptr);
    sgemm128<128, 8><<<dim3(6, 48, 1), 256>>>(x, DD, 0, Vw, HH * DVc, 0, 0,
                                              pV, HH * DVc, 0, 0, BB * LL, HH * DVc, DD, 1.0f, nullptr);

    // 4. fused content + shifted-rel scores -> logits
    score_kernel<<<dim3(24, 24, 32), 256>>>(pQ, pK, prK, rwb, rrb, plog);

    // 5. softmax over j
    softmax_kernel<<<BB * HH * LL, 256>>>(plog);

    // 6. attn = P @ V, batched over (b,h)
    sgemm128<96, 6><<<dim3(1, 12, 32), 256>>>(plog, LL, (long long)LL * LL,
                                              pV, HH * DVc, (long long)LL * HH * DVc, DVc,
                                              pattn, HH * DVc, (long long)LL * HH * DVc, DVc,
                                              LL, DVc, LL, 1.0f, nullptr);

    // 7. out = attn @ out_w + out_b  -> d_out
    sgemm128<128, 8><<<dim3(6, 48, 1), 256>>>(pattn, DD, 0, outw, DD, 0, 0,
                                              (float*)d_out, DD, 0, 0, BB * LL, DD, DD, 1.0f, outb);
}

// round 4
// speedup vs baseline: 2.5817x; 1.7830x over previous
#include <cuda_runtime.h>
#include <cuda_bf16.h>
#include <math.h>

#define BB 4
#define LL 1536
#define DD 768
#define HH 8
#define DQKc 64
#define DVc 96
#define NPOS 3071   // 2L-1

typedef __nv_bfloat16 bf16;

// ---------------- scratch (static device globals; no allocation) ----------------
__device__ bf16 g_xh[(size_t)BB * LL * DD],      g_xl[(size_t)BB * LL * DD];
__device__ bf16 g_QwTh[512 * 768],               g_QwTl[512 * 768];
__device__ bf16 g_KwTh[512 * 768],               g_KwTl[512 * 768];
__device__ bf16 g_VwTh[768 * 768],               g_VwTl[768 * 768];
__device__ bf16 g_OwTh[768 * 768],               g_OwTl[768 * 768];
__device__ bf16 g_RwTh[512 * 96],                g_RwTl[512 * 96];
__device__ bf16 g_peh[(size_t)NPOS * 96],        g_pel[(size_t)NPOS * 96];
__device__ bf16 g_rKh[(size_t)3072 * 512],       g_rKl[(size_t)3072 * 512];
__device__ bf16 g_Qh[(size_t)BB * LL * 512],     g_Ql[(size_t)BB * LL * 512];   // Q*0.125 + rwb
__device__ bf16 g_Kh[(size_t)BB * LL * 512],     g_Kl[(size_t)BB * LL * 512];
__device__ float g_V[(size_t)BB * LL * 768];
__device__ bf16 g_Vth[(size_t)32 * 96 * LL],     g_Vtl[(size_t)32 * 96 * LL];   // V^T per (b,h)
__device__ float g_sbd[8 * NPOS];                                              // delta . rK
__device__ float g_logits[(size_t)32 * LL * LL];
__device__ bf16 g_Ph[(size_t)32 * LL * LL],      g_Pl[(size_t)32 * LL * LL];
__device__ bf16 g_ah[(size_t)BB * LL * 768],     g_al[(size_t)BB * LL * 768];   // attn

// ---------------- small helpers ----------------
__device__ __forceinline__ unsigned smaddr(const void* p) {
    return (unsigned)__cvta_generic_to_shared(p);
}
__device__ __forceinline__ void ldsmx4(unsigned* r, unsigned a) {
    asm volatile("ldmatrix.sync.aligned.m8n8.x4.shared.b16 {%0,%1,%2,%3},[%4];\n"
        : "=r"(r[0]), "=r"(r[1]), "=r"(r[2]), "=r"(r[3]) : "r"(a));
}
__device__ __forceinline__ void ldsmx2(unsigned* r, unsigned a) {
    asm volatile("ldmatrix.sync.aligned.m8n8.x2.shared.b16 {%0,%1},[%2];\n"
        : "=r"(r[0]), "=r"(r[1]) : "r"(a));
}
__device__ __forceinline__ void mma16816(float* c, const unsigned* a, const unsigned* b) {
    asm volatile("mma.sync.aligned.m16n8k16.row.col.f32.bf16.bf16.f32 "
        "{%0,%1,%2,%3},{%4,%5,%6,%7},{%8,%9},{%0,%1,%2,%3};\n"
        : "+f"(c[0]), "+f"(c[1]), "+f"(c[2]), "+f"(c[3])
        : "r"(a[0]), "r"(a[1]), "r"(a[2]), "r"(a[3]), "r"(b[0]), "r"(b[1]));
}
__device__ __forceinline__ void f2split(float v, bf16& h, bf16& l) {
    h = __float2bfloat16(v);
    l = __float2bfloat16(v - __bfloat162float(h));
}

// ---------------- positional features (write split bf16) ----------------
__device__ __forceinline__ float gamma_pdf(float x, float cm1, float rate, float lognorm) {
    if (x <= 0.0f) return 0.0f;
    return expf(cm1 * logf(x) - rate * x - lognorm);
}

__global__ void pe_kernel(bf16* __restrict__ peh, bf16* __restrict__ pel) {
    int idx = blockIdx.x * blockDim.x + threadIdx.x;
    if (idx >= NPOS) return;
    float p = (float)(idx - (LL - 1));
    float ap = fabsf(p);
    float sg = (p > 0.f) ? 1.f : ((p < 0.f) ? -1.f : 0.f);
    float max_range = log2f((float)LL);
    size_t base = (size_t)idx * 96;
    #pragma unroll 1
    for (int i = 0; i < 16; i++) {
        float hl = exp2f(3.0f + (max_range - 3.0f) * (float)i * (1.0f / 15.0f));
        float fe = exp2f(-ap / hl);
        float cw = exp2f((float)(i + 1)) - 1.0f;
        float fc = (cw > ap) ? 1.0f : 0.0f;
        float k1 = (float)(i + 1);
        float conc = 4.0f * k1 * k1;
        float rate = k1 * (1.0f / 24.0f);
        float lognorm = lgammaf(conc) - conc * logf(rate);
        float cm1 = conc - 1.0f;
        float mode = cm1 / rate;
        float t0 = fminf(fmaxf(floorf(mode), 0.0f), (float)(LL - 1));
        float t1 = fminf(t0 + 1.0f, (float)(LL - 1));
        float mx = fmaxf(gamma_pdf(t0, cm1, rate, lognorm),
                         gamma_pdf(t1, cm1, rate, lognorm)) + 1e-8f;
        float fg = (gamma_pdf(ap, cm1, rate, lognorm) + 1e-8f) / mx;
        float vals[6] = {fe, fc, fg, sg * fe, sg * fc, sg * fg};
        #pragma unroll
        for (int s = 0; s < 6; s++) {
            bf16 h, l; f2split(vals[s], h, l);
            peh[base + s * 16 + i] = h; pel[base + s * 16 + i] = l;
        }
    }
}

// ---------------- elementwise convert x -> split ----------------
__global__ void convx_kernel(const float* __restrict__ in, bf16* __restrict__ oh,
                             bf16* __restrict__ ol, int n) {
    int idx = blockIdx.x * blockDim.x + threadIdx.x;
    if (idx >= n) return;
    bf16 h, l; f2split(in[idx], h, l);
    oh[idx] = h; ol[idx] = l;
}

// ---------------- transpose + convert: in fp32 [R][Cn] -> out split [Cn][R] ----------------
__global__ void tconv_kernel(const float* __restrict__ in, bf16* __restrict__ oh,
                             bf16* __restrict__ ol, int R, int Cn) {
    __shared__ float ts[32][33];
    int c0 = blockIdx.x * 32, r0 = blockIdx.y * 32;
    int tx = threadIdx.x, ty = threadIdx.y;
    #pragma unroll
    for (int t = 0; t < 4; t++)
        ts[ty + t * 8][tx] = in[(size_t)(r0 + ty + t * 8) * Cn + c0 + tx];
    __syncthreads();
    #pragma unroll
    for (int t = 0; t < 4; t++) {
        float v = ts[tx][ty + t * 8];
        size_t o = (size_t)(c0 + ty + t * 8) * R + r0 + tx;
        bf16 h, l; f2split(v, h, l);
        oh[o] = h; ol[o] = l;
    }
}

// ---------------- V transpose per (b,h): fp32 [b*L+j][h*96+dv] -> split [z][dv][j] ----------------
__global__ void vtrans_kernel(const float* __restrict__ V, bf16* __restrict__ oh,
                              bf16* __restrict__ ol) {
    __shared__ float ts[32][33];
    int z = blockIdx.z, b = z >> 3, h = z & 7;
    int jb = blockIdx.x * 32, db = blockIdx.y * 32;
    int tx = threadIdx.x, ty = threadIdx.y;
    #pragma unroll
    for (int t = 0; t < 4; t++)
        ts[ty + t * 8][tx] = V[(size_t)(b * LL + jb + ty + t * 8) * 768 + h * 96 + db + tx];
    __syncthreads();
    #pragma unroll
    for (int t = 0; t < 4; t++) {
        float v = ts[tx][ty + t * 8];
        size_t o = (size_t)z * 96 * LL + (size_t)(db + ty + t * 8) * LL + jb + tx;
        bf16 h2, l2; f2split(v, h2, l2);
        oh[o] = h2; ol[o] = l2;
    }
}

// ---------------- sbd[h][p] = (rrb_h - rwb_h) . rK[p, h, :] ----------------
__global__ void sbd_kernel(const bf16* __restrict__ Rh, const bf16* __restrict__ Rl,
                           const float* __restrict__ rwb, const float* __restrict__ rrb,
                           float* __restrict__ outp) {
    int idx = blockIdx.x * blockDim.x + threadIdx.x;
    if (idx >= 8 * NPOS) return;
    int h = idx / NPOS, p = idx % NPOS;
    float s = 0.0f;
    #pragma unroll 8
    for (int d = 0; d < 64; d++) {
        size_t o = (size_t)p * 512 + h * 64 + d;
        s += (rrb[h * 64 + d] - rwb[h * 64 + d]) *
             (__bfloat162float(Rh[o]) + __bfloat162float(Rl[o]));
    }
    outp[idx] = s;
}

// ---------------- generic split-bf16 tensor-core GEMM: C = alpha*A.B^T + bias ----------------
// A split [M][K] row-major, B split [N][K] row-major. BM=128, BK=32, 256 threads.
template<int BN, bool SPLIT>
__global__ __launch_bounds__(256) void hgemm(
    const bf16* __restrict__ Ah, const bf16* __restrict__ Al, int lda,
    long long sA1, long long sA2,
    const bf16* __restrict__ Bh, const bf16* __restrict__ Bl, int ldb,
    long long sB1, long long sB2,
    float* __restrict__ Cf, bf16* __restrict__ Ch, bf16* __restrict__ Cl, int ldc,
    long long sC1, long long sC2,
    int M, int K, float alpha, const float* __restrict__ bias)
{
    constexpr int PAD = 40;
    constexpr int NT = BN / 16;            // n-tiles per warp
    constexpr int NBLD = (BN * 4 + 255) / 256;
    __shared__ __align__(16) bf16 sAh[128 * PAD], sAl[128 * PAD];
    __shared__ __align__(16) bf16 sBh[BN * PAD],  sBl[BN * PAD];

    int z = blockIdx.z, zb = z >> 3, zh = z & 7;
    Ah += (size_t)zb * sA1 + (size_t)zh * sA2;
    Al += (size_t)zb * sA1 + (size_t)zh * sA2;
    Bh += (size_t)zb * sB1 + (size_t)zh * sB2;
    Bl += (size_t)zb * sB1 + (size_t)zh * sB2;
    size_t coff = (size_t)zb * sC1 + (size_t)zh * sC2;

    int i0 = blockIdx.y * 128, j0 = blockIdx.x * BN;
    int tid = threadIdx.x, warp = tid >> 5, lane = tid & 31;
    int wm = warp >> 1, wn = warp & 1;
    int m0 = wm * 32, n0 = wn * (BN / 2);

    float acc[2][NT][4] = {};

    for (int kk = 0; kk < K; kk += 32) {
        uint4 avh[2], avl[2], bvh[NBLD], bvl[NBLD];
        #pragma unroll
        for (int t = 0; t < 2; t++) {
            int idx = tid + t * 256;
            int row = idx >> 2, c16 = idx & 3;
            int gr = i0 + row;
            if (gr < M) {
                avh[t] = *(const uint4*)(Ah + (size_t)gr * lda + kk + c16 * 8);
                avl[t] = *(const uint4*)(Al + (size_t)gr * lda + kk + c16 * 8);
            } else {
                avh[t] = make_uint4(0, 0, 0, 0); avl[t] = make_uint4(0, 0, 0, 0);
            }
        }
        #pragma unroll
        for (int t = 0; t < NBLD; t++) {
            int idx = tid + t * 256;
            if (idx < BN * 4) {
                int row = idx >> 2, c16 = idx & 3;
                bvh[t] = *(const uint4*)(Bh + (size_t)(j0 + row) * ldb + kk + c16 * 8);
                bvl[t] = *(const uint4*)(Bl + (size_t)(j0 + row) * ldb + kk + c16 * 8);
            }
        }
        __syncthreads();
        #pragma unroll
        for (int t = 0; t < 2; t++) {
            int idx = tid + t * 256;
            int row = idx >> 2, c16 = idx & 3;
            *(uint4*)(sAh + row * PAD + c16 * 8) = avh[t];
            *(uint4*)(sAl + row * PAD + c16 * 8) = avl[t];
        }
        #pragma unroll
        for (int t = 0; t < NBLD; t++) {
            int idx = tid + t * 256;
            if (idx < BN * 4) {
                int row = idx >> 2, c16 = idx & 3;
                *(uint4*)(sBh + row * PAD + c16 * 8) = bvh[t];
                *(uint4*)(sBl + row * PAD + c16 * 8) = bvl[t];
            }
        }
        __syncthreads();
        #pragma unroll
        for (int ks = 0; ks < 2; ks++) {
            int kb = ks * 16;
            unsigned ah[2][4], al[2][4], bh[NT][2], bl[NT][2];
            #pragma unroll
            for (int mt = 0; mt < 2; mt++) {
                int arow = m0 + mt * 16 + (lane & 15);
                int acol = kb + (lane >> 4) * 8;
                ldsmx4(ah[mt], smaddr(sAh + arow * PAD + acol));
                ldsmx4(al[mt], smaddr(sAl + arow * PAD + acol));
            }
            #pragma unroll
            for (int nt = 0; nt < NT; nt++) {
                int brow = n0 + nt * 8 + (lane & 7);
                int bcol = kb + ((lane >> 3) & 1) * 8;
                ldsmx2(bh[nt], smaddr(sBh + brow * PAD + bcol));
                ldsmx2(bl[nt], smaddr(sBl + brow * PAD + bcol));
            }
            #pragma unroll
            for (int mt = 0; mt < 2; mt++)
                #pragma unroll
                for (int nt = 0; nt < NT; nt++) {
                    mma16816(acc[mt][nt], ah[mt], bh[nt]);
                    mma16816(acc[mt][nt], ah[mt], bl[nt]);
                    mma16816(acc[mt][nt], al[mt], bh[nt]);
                }
        }
        __syncthreads();
    }

    // epilogue
    #pragma unroll
    for (int mt = 0; mt < 2; mt++)
        #pragma unroll
        for (int nt = 0; nt < NT; nt++) {
            int r0 = i0 + m0 + mt * 16 + (lane >> 2);
            int jn = j0 + n0 + nt * 8 + ((lane & 3) << 1);
            float b0 = bias ? bias[jn] : 0.0f;
            float b1 = bias ? bias[jn + 1] : 0.0f;
            float v00 = alpha * acc[mt][nt][0] + b0;
            float v01 = alpha * acc[mt][nt][1] + b1;
            float v10 = alpha * acc[mt][nt][2] + b0;
            float v11 = alpha * acc[mt][nt][3] + b1;
            if (SPLIT) {
                bf16 h0, l0, h1, l1;
                if (r0 < M) {
                    f2split(v00, h0, l0); f2split(v01, h1, l1);
                    __nv_bfloat162 hh; hh.x = h0; hh.y = h1;
                    __nv_bfloat162 ll; ll.x = l0; ll.y = l1;
                    *(__nv_bfloat162*)(Ch + coff + (size_t)r0 * ldc + jn) = hh;
                    *(__nv_bfloat162*)(Cl + coff + (size_t)r0 * ldc + jn) = ll;
                }
                if (r0 + 8 < M) {
                    f2split(v10, h0, l0); f2split(v11, h1, l1);
                    __nv_bfloat162 hh; hh.x = h0; hh.y = h1;
                    __nv_bfloat162 ll; ll.x = l0; ll.y = l1;
                    *(__nv_bfloat162*)(Ch + coff + (size_t)(r0 + 8) * ldc + jn) = hh;
                    *(__nv_bfloat162*)(Cl + coff + (size_t)(r0 + 8) * ldc + jn) = ll;
                }
            } else {
                if (r0 < M)
                    *(float2*)(Cf + coff + (size_t)r0 * ldc + jn) = make_float2(v00, v01);
                if (r0 + 8 < M)
                    *(float2*)(Cf + coff + (size_t)(r0 + 8) * ldc + jn) = make_float2(v10, v11);
            }
        }
}

// ---------------- score: content (64 cols) + band (128 cols) in one mma GEMM ----------------
// logits[z,i,j] = Qp_i.K_j + Qp_i.rK_{L-1+j-i} + sbd[h][L-1+j-i],  Qp = Q*0.125 + rwb
__global__ __launch_bounds__(256) void score_mma(
    const bf16* __restrict__ Qh, const bf16* __restrict__ Ql,
    const bf16* __restrict__ Kh, const bf16* __restrict__ Kl,
    const bf16* __restrict__ Rh, const bf16* __restrict__ Rl,
    const float* __restrict__ sbd_g, float* __restrict__ logits)
{
    __shared__ __align__(16) unsigned char smem_raw[41984];
    bf16* sAh = (bf16*)(smem_raw);           // 64*40*2   = 5120 B
    bf16* sAl = (bf16*)(smem_raw + 5120);
    bf16* sBh = (bf16*)(smem_raw + 10240);   // 192*40*2  = 15360 B
    bf16* sBl = (bf16*)(smem_raw + 25600);   // end 40960
    float* C2s = (float*)smem_raw;           // union: 64*130*4 = 33280 B

    int tid = threadIdx.x, warp = tid >> 5, lane = tid & 31;
    int z = blockIdx.z, b = z >> 3, h = z & 7;
    int i0 = blockIdx.y * 64, j0 = blockIdx.x * 64;
    int k0 = 1472 + j0 - i0;                          // band row r -> rK row k0+r
    size_t qkbase = ((size_t)b * LL) * 512 + h * 64;
    const float* sbd = sbd_g + h * NPOS;

    int wm = warp >> 2, wn = warp & 3;
    int m0 = wm * 32, n0 = wn * 48;

    float acc[2][6][4] = {};

    for (int kk = 0; kk < 64; kk += 32) {
        // gmem -> regs
        int arow = tid >> 2, ac16 = tid & 3;
        uint4 avh = *(const uint4*)(Qh + qkbase + (size_t)(i0 + arow) * 512 + kk + ac16 * 8);
        uint4 avl = *(const uint4*)(Ql + qkbase + (size_t)(i0 + arow) * 512 + kk + ac16 * 8);
        uint4 bvh[3], bvl[3];
        #pragma unroll
        for (int t = 0; t < 3; t++) {
            int idx = tid + t * 256;
            int row = idx >> 2, c16 = idx & 3;
            if (row < 64) {
                bvh[t] = *(const uint4*)(Kh + qkbase + (size_t)(j0 + row) * 512 + kk + c16 * 8);
                bvl[t] = *(const uint4*)(Kl + qkbase + (size_t)(j0 + row) * 512 + kk + c16 * 8);
            } else {
                size_t ro = (size_t)(k0 + row - 64) * 512 + h * 64 + kk + c16 * 8;
                bvh[t] = *(const uint4*)(Rh + ro);
                bvl[t] = *(const uint4*)(Rl + ro);
            }
        }
        __syncthreads();
        *(uint4*)(sAh + arow * 40 + ac16 * 8) = avh;
        *(uint4*)(sAl + arow * 40 + ac16 * 8) = avl;
        #pragma unroll
        for (int t = 0; t < 3; t++) {
            int idx = tid + t * 256;
            int row = idx >> 2, c16 = idx & 3;
            *(uint4*)(sBh + row * 40 + c16 * 8) = bvh[t];
            *(uint4*)(sBl + row * 40 + c16 * 8) = bvl[t];
        }
        __syncthreads();
        #pragma unroll
        for (int ks = 0; ks < 2; ks++) {
            int kb = ks * 16;
            unsigned ah[2][4], al[2][4], bh[6][2], bl[6][2];
            #pragma unroll
            for (int mt = 0; mt < 2; mt++) {
                int ar = m0 + mt * 16 + (lane & 15);
                int acl = kb + (lane >> 4) * 8;
                ldsmx4(ah[mt], smaddr(sAh + ar * 40 + acl));
                ldsmx4(al[mt], smaddr(sAl + ar * 40 + acl));
            }
            #pragma unroll
            for (int nt = 0; nt < 6; nt++) {
                int br = n0 + nt * 8 + (lane & 7);
                int bcl = kb + ((lane >> 3) & 1) * 8;
                ldsmx2(bh[nt], smaddr(sBh + br * 40 + bcl));
                ldsmx2(bl[nt], smaddr(sBl + br * 40 + bcl));
            }
            #pragma unroll
            for (int mt = 0; mt < 2; mt++)
                #pragma unroll
                for (int nt = 0; nt < 6; nt++) {
                    mma16816(acc[mt][nt], ah[mt], bh[nt]);
                    mma16816(acc[mt][nt], ah[mt], bl[nt]);
                    mma16816(acc[mt][nt], al[mt], bh[nt]);
                }
        }
        __syncthreads();
    }

    // band tiles -> smem
    #pragma unroll
    for (int mt = 0; mt < 2; mt++)
        #pragma unroll
        for (int nt = 0; nt < 6; nt++) {
            int nA = n0 + nt * 8;
            if (nA >= 64) {
                int col = nA - 64 + ((lane & 3) << 1);
                int rr = m0 + mt * 16 + (lane >> 2);
                C2s[rr * 130 + col]           = acc[mt][nt][0];
                C2s[rr * 130 + col + 1]       = acc[mt][nt][1];
                C2s[(rr + 8) * 130 + col]     = acc[mt][nt][2];
                C2s[(rr + 8) * 130 + col + 1] = acc[mt][nt][3];
            }
        }
    __syncthreads();

    float* out = logits + (size_t)z * LL * LL;
    #pragma unroll
    for (int mt = 0; mt < 2; mt++)
        #pragma unroll
        for (int nt = 0; nt < 6; nt++) {
            int nA = n0 + nt * 8;
            if (nA < 64) {
                int ii = m0 + mt * 16 + (lane >> 2);
                int jj = nA + ((lane & 3) << 1);
                {
                    int r = jj - ii + 63;
                    float v0 = acc[mt][nt][0] + C2s[ii * 130 + r] + sbd[k0 + r];
                    float v1 = acc[mt][nt][1] + C2s[ii * 130 + r + 1] + sbd[k0 + r + 1];
                    *(float2*)(out + (size_t)(i0 + ii) * LL + j0 + jj) = make_float2(v0, v1);
                }
                {
                    int i2 = ii + 8;
                    int r = jj - i2 + 63;
                    float v0 = acc[mt][nt][2] + C2s[i2 * 130 + r] + sbd[k0 + r];
                    float v1 = acc[mt][nt][3] + C2s[i2 * 130 + r + 1] + sbd[k0 + r + 1];
                    *(float2*)(out + (size_t)(i0 + i2) * LL + j0 + jj) = make_float2(v0, v1);
                }
            }
        }
}

// ---------------- row softmax -> split bf16 P ----------------
__global__ __launch_bounds__(256) void softmax_kernel(const float* __restrict__ logits,
                                                      bf16* __restrict__ Ph,
                                                      bf16* __restrict__ Pl) {
    __shared__ float red[256];
    size_t row = blockIdx.x;
    const float* p = logits + row * LL;
    int tid = threadIdx.x;
    float v[6];
    float mx = -1e30f;
    #pragma unroll
    for (int t = 0; t < 6; t++) { v[t] = p[tid + t * 256]; mx = fmaxf(mx, v[t]); }
    red[tid] = mx; __syncthreads();
    for (int s = 128; s > 0; s >>= 1) {
        if (tid < s) red[tid] = fmaxf(red[tid], red[tid + s]);
        __syncthreads();
    }
    mx = red[0]; __syncthreads();
    float sum = 0.0f;
    #pragma unroll
    for (int t = 0; t < 6; t++) { v[t] = expf(v[t] - mx); sum += v[t]; }
    red[tid] = sum; __syncthreads();
    for (int s = 128; s > 0; s >>= 1) {
        if (tid < s) red[tid] += red[tid + s];
        __syncthreads();
    }
    float inv = 1.0f / red[0];
    #pragma unroll
    for (int t = 0; t < 6; t++) {
        float val = v[t] * inv;
        bf16 h, l; f2split(val, h, l);
        Ph[row * LL + tid + t * 256] = h;
        Pl[row * LL + tid + t * 256] = l;
    }
}

// ---------------- launch ----------------
extern "C" void kernel_launch(void* const* d_in, const int* in_sizes, int n_in,
                              void* d_out, int out_size) {
    (void)in_sizes; (void)n_in; (void)out_size;
    const float* x     = (const float*)d_in[0];
    const float* Qw    = (const float*)d_in[1];
    const float* Kw    = (const float*)d_in[2];
    const float* Vw    = (const float*)d_in[3];
    const float* outw  = (const float*)d_in[4];
    const float* outb  = (const float*)d_in[5];
    const float* relKw = (const float*)d_in[6];
    const float* rwb   = (const float*)d_in[7];
    const float* rrb   = (const float*)d_in[8];

    bf16 *xh, *xl, *QwTh, *QwTl, *KwTh, *KwTl, *VwTh, *VwTl, *OwTh, *OwTl, *RwTh, *RwTl;
    bf16 *peh, *pel, *rKh, *rKl, *Qh, *Ql, *Kh, *Kl, *Vth, *Vtl, *Ph, *Pl, *ath, *atl;
    float *V, *sbd, *logits;
    cudaGetSymbolAddress((void**)&xh, g_xh);     cudaGetSymbolAddress((void**)&xl, g_xl);
    cudaGetSymbolAddress((void**)&QwTh, g_QwTh); cudaGetSymbolAddress((void**)&QwTl, g_QwTl);
    cudaGetSymbolAddress((void**)&KwTh, g_KwTh); cudaGetSymbolAddress((void**)&KwTl, g_KwTl);
    cudaGetSymbolAddress((void**)&VwTh, g_VwTh); cudaGetSymbolAddress((void**)&VwTl, g_VwTl);
    cudaGetSymbolAddress((void**)&OwTh, g_OwTh); cudaGetSymbolAddress((void**)&OwTl, g_OwTl);
    cudaGetSymbolAddress((void**)&RwTh, g_RwTh); cudaGetSymbolAddress((void**)&RwTl, g_RwTl);
    cudaGetSymbolAddress((void**)&peh, g_peh);   cudaGetSymbolAddress((void**)&pel, g_pel);
    cudaGetSymbolAddress((void**)&rKh, g_rKh);   cudaGetSymbolAddress((void**)&rKl, g_rKl);
    cudaGetSymbolAddress((void**)&Qh, g_Qh);     cudaGetSymbolAddress((void**)&Ql, g_Ql);
    cudaGetSymbolAddress((void**)&Kh, g_Kh);     cudaGetSymbolAddress((void**)&Kl, g_Kl);
    cudaGetSymbolAddress((void**)&V, g_V);
    cudaGetSymbolAddress((void**)&Vth, g_Vth);   cudaGetSymbolAddress((void**)&Vtl, g_Vtl);
    cudaGetSymbolAddress((void**)&sbd, g_sbd);
    cudaGetSymbolAddress((void**)&logits, g_logits);
    cudaGetSymbolAddress((void**)&Ph, g_Ph);     cudaGetSymbolAddress((void**)&Pl, g_Pl);
    cudaGetSymbolAddress((void**)&ath, g_ah);    cudaGetSymbolAddress((void**)&atl, g_al);

    dim3 tb(32, 8);

    // conversions + positional features
    pe_kernel<<<(NPOS + 127) / 128, 128>>>(peh, pel);
    convx_kernel<<<(BB * LL * DD + 255) / 256, 256>>>(x, xh, xl, BB * LL * DD);
    tconv_kernel<<<dim3(16, 24), tb>>>(Qw, QwTh, QwTl, 768, 512);
    tconv_kernel<<<dim3(16, 24), tb>>>(Kw, KwTh, KwTl, 768, 512);
    tconv_kernel<<<dim3(24, 24), tb>>>(Vw, VwTh, VwTl, 768, 768);
    tconv_kernel<<<dim3(24, 24), tb>>>(outw, OwTh, OwTl, 768, 768);
    tconv_kernel<<<dim3(16, 3),  tb>>>(relKw, RwTh, RwTl, 96, 512);

    // rK = pe @ relKw : [3071][512], K=96 -> split
    hgemm<64, true><<<dim3(8, 24, 1), 256>>>(peh, pel, 96, 0, 0, RwTh, RwTl, 96, 0, 0,
        nullptr, rKh, rKl, 512, 0, 0, NPOS, 96, 1.0f, nullptr);
    sbd_kernel<<<(8 * NPOS + 255) / 256, 256>>>(rKh, rKl, rwb, rrb, sbd);

    // projections
    hgemm<64, true><<<dim3(8, 48, 1), 256>>>(xh, xl, 768, 0, 0, QwTh, QwTl, 768, 0, 0,
        nullptr, Qh, Ql, 512, 0, 0, BB * LL, 768, 0.125f, rwb);
    hgemm<64, true><<<dim3(8, 48, 1), 256>>>(xh, xl, 768, 0, 0, KwTh, KwTl, 768, 0, 0,
        nullptr, Kh, Kl, 512, 0, 0, BB * LL, 768, 1.0f, nullptr);
    hgemm<64, false><<<dim3(12, 48, 1), 256>>>(xh, xl, 768, 0, 0, VwTh, VwTl, 768, 0, 0,
        V, nullptr, nullptr, 768, 0, 0, BB * LL, 768, 1.0f, nullptr);
    vtrans_kernel<<<dim3(48, 3, 32), tb>>>(V, Vth, Vtl);

    // scores + softmax
    score_mma<<<dim3(24, 24, 32), 256>>>(Qh, Ql, Kh, Kl, rKh, rKl, sbd, logits);
    softmax_kernel<<<32 * LL, 256>>>(logits, Ph, Pl);

    // attn = P @ V  (batched over z; B = V^T)
    hgemm<96, true><<<dim3(1, 12, 32), 256>>>(
        Ph, Pl, LL, (long long)8 * LL * LL, (long long)LL * LL,
        Vth, Vtl, LL, (long long)8 * 96 * LL, (long long)96 * LL,
        nullptr, ath, atl, 768, (long long)LL * 768, 96,
        LL, LL, 1.0f, nullptr);

    // out = attn @ outw + outb
    hgemm<64, false><<<dim3(12, 48, 1), 256>>>(ath, atl, 768, 0, 0, OwTh, OwTl, 768, 0, 0,
        (float*)d_out, nullptr, nullptr, 768, 0, 0, BB * LL, 768, 1.0f, outb);
}